// round 6
// baseline (speedup 1.0000x reference)
#include <cuda_runtime.h>
#include <math.h>

#define N_NODES   512
#define IN_FEAT   512
#define N_HEADS   8
#define N_HID     64

typedef unsigned long long u64;

// Scratch (device globals: allocation-free rule)
__device__ float d_gsrc[N_HEADS * N_NODES * N_HID];   // [h][n][f]
__device__ float d_gtgt[N_HEADS * N_NODES * N_HID];   // [h][n][f]
__device__ float d_attn[N_HEADS * N_NODES * N_NODES]; // [h][i][j]
__device__ float d_u[N_HEADS * N_NODES];              // 0.6 * <w, gsrc[j]>
__device__ float d_v[N_HEADS * N_NODES];              // 0.6 * <w, gtgt[i]>
__device__ u64   d_gspk[N_HEADS * 32 * N_NODES];      // [h][fp][j] packed f-pairs

// ---- packed f32x2 helpers ----
__device__ __forceinline__ u64 pack2(float x, float y) {
    u64 r; asm("mov.b64 %0, {%1,%2};" : "=l"(r) : "f"(x), "f"(y)); return r;
}
__device__ __forceinline__ void unpack2(u64 v, float& x, float& y) {
    asm("mov.b64 {%0,%1}, %2;" : "=f"(x), "=f"(y) : "l"(v));
}
__device__ __forceinline__ u64 add2(u64 a, u64 b) {
    u64 d; asm("add.rn.f32x2 %0, %1, %2;" : "=l"(d) : "l"(a), "l"(b)); return d;
}
__device__ __forceinline__ u64 fma2(u64 a, u64 b, u64 c) {
    u64 d; asm("fma.rn.f32x2 %0, %1, %2, %3;" : "=l"(d) : "l"(a), "l"(b), "l"(c)); return d;
}

// ---------------------------------------------------------------------------
// K1: g = x @ W^T for both weights. 64n x 64r tile, 512 threads,
// 2-row x 4-col micro-tile. A pre-duplicated as (a,a) u64 pairs in smem.
// Epilogue: g rows + u/v = 0.6*<attn_w, row>.
// ---------------------------------------------------------------------------
__global__ __launch_bounds__(512) void k1_gemm(const float* __restrict__ x,
                                               const float* __restrict__ Ws,
                                               const float* __restrict__ Wt,
                                               const float* __restrict__ aw) {
    __shared__ u64   At2[16][65];  // [d][n] duplicated pairs
    __shared__ float Bt[16][68];   // [d][j]

    const int n0 = blockIdx.x * 64;
    const int r0 = blockIdx.y * 64;           // 0..1023
    const float* W    = (r0 < 512) ? Ws : Wt;
    float*       gout = (r0 < 512) ? d_gsrc : d_gtgt;
    float*       uv   = (r0 < 512) ? d_u : d_v;
    const int rb = r0 & 511;
    const int h  = rb >> 6;

    const int t  = threadIdx.x;
    const int tx = t & 15, ty = t >> 4;       // rows 2ty,2ty+1; cols 4tx..4tx+3

    u64 acc[2][2] = {};

    for (int k0 = 0; k0 < IN_FEAT; k0 += 16) {
        #pragma unroll
        for (int kk = 0; kk < 2; kk++) {
            const int lin = t + kk * 512;
            const int d = lin & 15, n = lin >> 4;
            const float a = x[(n0 + n) * IN_FEAT + k0 + d];
            At2[d][n] = pack2(a, a);
            Bt[d][n]  = W[(rb + n) * IN_FEAT + k0 + d];
        }
        __syncthreads();
        #pragma unroll
        for (int d2 = 0; d2 < 16; d2++) {
            const u64 a0 = At2[d2][2 * ty];
            const u64 a1 = At2[d2][2 * ty + 1];
            const u64* bp = (const u64*)&Bt[d2][4 * tx];
            const u64 b0 = bp[0], b1 = bp[1];
            acc[0][0] = fma2(a0, b0, acc[0][0]);
            acc[0][1] = fma2(a0, b1, acc[0][1]);
            acc[1][0] = fma2(a1, b0, acc[1][0]);
            acc[1][1] = fma2(a1, b1, acc[1][1]);
        }
        __syncthreads();
    }

    const float w0 = 0.6f * aw[4 * tx],     w1 = 0.6f * aw[4 * tx + 1];
    const float w2 = 0.6f * aw[4 * tx + 2], w3 = 0.6f * aw[4 * tx + 3];

    #pragma unroll
    for (int ii = 0; ii < 2; ii++) {
        const int n = n0 + 2 * ty + ii;
        float* dst = gout + h * (N_NODES * N_HID) + n * N_HID;
        float c0, c1, c2, c3;
        unpack2(acc[ii][0], c0, c1);
        unpack2(acc[ii][1], c2, c3);
        *(float4*)&dst[4 * tx] = make_float4(c0, c1, c2, c3);
        float p = w0 * c0 + w1 * c1 + w2 * c2 + w3 * c3;
        #pragma unroll
        for (int off = 8; off; off >>= 1)
            p += __shfl_down_sync(0xffffffffu, p, off, 16);
        if (tx == 0) uv[h * N_NODES + n] = p;
    }
}

// ---------------------------------------------------------------------------
// K2pre: repack d_gsrc[h][j][f] -> d_gspk[h][fp][j] (f-pair-major u64).
// Two kernels (h-halves) so k2 lands on profiler launch slot idx5.
// ---------------------------------------------------------------------------
__global__ __launch_bounds__(256) void k2pre(int hbase) {
    const int lin = blockIdx.x * 256 + threadIdx.x;   // 0..32767
    const int h  = hbase + (lin >> 13);
    const int f4 = (lin >> 9) & 15;
    const int j  = lin & 511;
    const float4 v = *(const float4*)&d_gsrc[(h * N_NODES + j) * N_HID + 4 * f4];
    d_gspk[h * 16384 + (2 * f4)     * 512 + j] = pack2(v.x, v.y);
    d_gspk[h * 16384 + (2 * f4 + 1) * 512 + j] = pack2(v.z, v.w);
}

// ---------------------------------------------------------------------------
// K2: A[i,j] = sum_f (0.4 w_f)|gs_jf + gt_if| (f32x2 + LOP3 abs), then
// score = A + u_j + v_i, adjacency mask, softmax over j -> d_attn[h][i][j].
// 512 threads; gs strip loaded pre-packed; scores stay in registers.
// ---------------------------------------------------------------------------
#define K2_SMEM_BYTES (32 * 512 * 8 + (32 * 66 + 64 + 512 + 32) * 4)

__global__ __launch_bounds__(512, 1) void k2_scores(const float* __restrict__ aw,
                                                    const int*   __restrict__ adj) {
    extern __shared__ char k2sm[];
    u64*   sgs = (u64*)k2sm;                       // [32 fp][512 j]
    float* sgt = (float*)(k2sm + 32 * 512 * 8);    // [32 i][66]
    float* sw  = sgt + 32 * 66;                    // 64 (0.4*w)
    float* su  = sw + 64;                          // 512
    float* sv  = su + 512;                         // 32

    const int h  = blockIdx.y;
    const int i0 = blockIdx.x * 32;
    const int t  = threadIdx.x;

    const float* gt_h = d_gtgt + h * (N_NODES * N_HID);

    if (t < 64) sw[t] = 0.4f * aw[t];
    su[t] = d_u[h * N_NODES + t];
    if (t < 32) sv[t] = d_v[h * N_NODES + i0 + t];

    #pragma unroll
    for (int k = 0; k < 4; k++) {
        const int lin = t + k * 512;
        const int i = lin >> 6, f = lin & 63;
        sgt[i * 66 + f] = gt_h[(i0 + i) * N_HID + f];
    }
    {
        const float4* src = (const float4*)(d_gspk + h * 16384);
        float4* dst = (float4*)sgs;
        #pragma unroll
        for (int k = 0; k < 16; k++)
            dst[t + k * 512] = src[t + k * 512];
    }
    __syncthreads();

    const int wid = t >> 5, tj = t & 31;       // warp wid owns rows 2wid, 2wid+1
    const u64 ABS2 = 0x7FFFFFFF7FFFFFFFULL;
    float vals[2][16];

    #pragma unroll
    for (int jt = 0; jt < 4; jt++) {
        u64 acc[2][4] = {};
        #pragma unroll 8
        for (int fp = 0; fp < 32; fp++) {
            const u64 w2 = *(const u64*)&sw[2 * fp];
            const u64 g0 = *(const u64*)&sgt[(2 * wid)     * 66 + 2 * fp];
            const u64 g1 = *(const u64*)&sgt[(2 * wid + 1) * 66 + 2 * fp];
            #pragma unroll
            for (int jj = 0; jj < 4; jj++) {
                const u64 s2 = sgs[fp * 512 + tj + 32 * (4 * jt + jj)];
                const u64 t0 = add2(g0, s2) & ABS2;
                const u64 t1 = add2(g1, s2) & ABS2;
                acc[0][jj] = fma2(t0, w2, acc[0][jj]);
                acc[1][jj] = fma2(t1, w2, acc[1][jj]);
            }
        }
        #pragma unroll
        for (int ii = 0; ii < 2; ii++)
            #pragma unroll
            for (int jj = 0; jj < 4; jj++) {
                float lo, hi; unpack2(acc[ii][jj], lo, hi);
                vals[ii][4 * jt + jj] = lo + hi;
            }
    }

    // Softmax per row (register-resident; lane tj holds j = tj + 32m)
    #pragma unroll
    for (int ii = 0; ii < 2; ii++) {
        const int i  = 2 * wid + ii;
        const int gi = i0 + i;
        const float svi = sv[i];
        const int* arow = adj + gi * N_NODES;

        float mx = -INFINITY;
        #pragma unroll
        for (int m = 0; m < 16; m++) {
            const int j = tj + 32 * m;
            float v = vals[ii][m] + su[j] + svi;
            v = arow[j] ? v : -INFINITY;
            vals[ii][m] = v;
            mx = fmaxf(mx, v);
        }
        #pragma unroll
        for (int o = 16; o; o >>= 1) mx = fmaxf(mx, __shfl_xor_sync(0xffffffffu, mx, o));

        float s = 0.f;
        #pragma unroll
        for (int m = 0; m < 16; m++) {
            const float e = __expf(vals[ii][m] - mx);
            vals[ii][m] = e;
            s += e;
        }
        #pragma unroll
        for (int o = 16; o; o >>= 1) s += __shfl_xor_sync(0xffffffffu, s, o);
        const float inv = 1.f / s;

        float* dst = d_attn + h * (N_NODES * N_NODES) + gi * N_NODES;
        #pragma unroll
        for (int m = 0; m < 16; m++)
            dst[tj + 32 * m] = vals[ii][m] * inv;
    }
}

// ---------------------------------------------------------------------------
// K3: out[i, h*64+f] = sum_j attn[h][i][j] * g_tgt[h][j][f]
// 512 threads; warp w owns rows 2w,2w+1; lane l owns f-pair 2l.
// attn pre-duplicated as (a,a) u64 pairs in smem.
// ---------------------------------------------------------------------------
__global__ __launch_bounds__(512) void k3_out(float* __restrict__ out) {
    __shared__ u64   sa2[32][33];
    __shared__ float sb[32][68];

    const int i0 = blockIdx.x * 32;
    const int h  = blockIdx.y;
    const int t  = threadIdx.x;
    const int w  = t >> 5, l = t & 31;

    const float* attn_h = d_attn + h * (N_NODES * N_NODES);
    const float* gt_h   = d_gtgt + h * (N_NODES * N_HID);

    u64 acc[2] = {};

    for (int j0 = 0; j0 < N_NODES; j0 += 32) {
        #pragma unroll
        for (int k = 0; k < 2; k++) {
            const int lin = t + k * 512;
            const int i = lin >> 5, j = lin & 31;
            const float a = attn_h[(i0 + i) * N_NODES + j0 + j];
            sa2[i][j] = pack2(a, a);
        }
        #pragma unroll
        for (int k = 0; k < 4; k++) {
            const int lin = t + k * 512;
            const int j = lin >> 6, f = lin & 63;
            sb[j][f] = gt_h[(j0 + j) * N_HID + f];
        }
        __syncthreads();
        #pragma unroll
        for (int j = 0; j < 32; j++) {
            const u64 a0 = sa2[2 * w][j];
            const u64 a1 = sa2[2 * w + 1][j];
            const u64 b  = *(const u64*)&sb[j][2 * l];
            acc[0] = fma2(a0, b, acc[0]);
            acc[1] = fma2(a1, b, acc[1]);
        }
        __syncthreads();
    }

    #pragma unroll
    for (int ii = 0; ii < 2; ii++) {
        const int i = i0 + 2 * w + ii;
        float lo, hi;
        unpack2(acc[ii], lo, hi);
        *(float2*)&out[i * 512 + h * N_HID + 2 * l] = make_float2(lo, hi);
    }
}

// ---------------------------------------------------------------------------
// K4: d_attn[h][i][j] -> attention [i][j][h]. Smem-staged, 2 rows per block,
// float4 both sides, conflict-free gather.
// ---------------------------------------------------------------------------
__global__ __launch_bounds__(512) void k4_transpose(float* __restrict__ att_out) {
    __shared__ float s[2][8][516];
    const int i0 = blockIdx.x * 2;
    const int t  = threadIdx.x;

    #pragma unroll
    for (int k = 0; k < 4; k++) {
        const int lin = t + k * 512;               // 0..2047 float4 slots
        const int i2 = lin >> 10, hh = (lin >> 7) & 7, j4 = lin & 127;
        const float4 v = *(const float4*)&d_attn[hh * (N_NODES * N_NODES) +
                                                 (i0 + i2) * N_NODES + 4 * j4];
        *(float4*)&s[i2][hh][4 * j4] = v;
    }
    __syncthreads();

    #pragma unroll
    for (int k = 0; k < 4; k++) {
        const int lin = t + k * 512;               // 0..2047 float4 slots
        const int i2 = lin >> 10, r = lin & 1023;
        const int j = r >> 1, h0 = (r & 1) * 4;
        const float4 v = make_float4(s[i2][h0 + 0][j], s[i2][h0 + 1][j],
                                     s[i2][h0 + 2][j], s[i2][h0 + 3][j]);
        *(float4*)&att_out[(i0 + i2) * (N_NODES * N_HEADS) + j * N_HEADS + h0] = v;
    }
}

// ---------------------------------------------------------------------------
extern "C" void kernel_launch(void* const* d_in, const int* in_sizes, int n_in,
                              void* d_out, int out_size) {
    const float* x   = (const float*)d_in[0];  // h [1,512,512]
    const float* Ws  = (const float*)d_in[1];  // W_source [512,512]
    const float* Wt  = (const float*)d_in[2];  // W_target [512,512]
    const float* aw  = (const float*)d_in[3];  // attn_w [64]
    const int*   adj = (const int*)d_in[4];    // adjacency [512,512,1]

    float* out = (float*)d_out;
    float* att_out = out + N_NODES * N_HEADS * N_HID;

    cudaFuncSetAttribute(k2_scores, cudaFuncAttributeMaxDynamicSharedMemorySize,
                         K2_SMEM_BYTES);

    k1_gemm<<<dim3(8, 16), 512>>>(x, Ws, Wt, aw);        // launch 1
    k2pre<<<128, 256>>>(0);                               // launch 2
    k2pre<<<128, 256>>>(4);                               // launch 3
    k2_scores<<<dim3(16, 8), 512, K2_SMEM_BYTES>>>(aw, adj);  // launch 4 -> idx5 (profiled)
    k3_out<<<dim3(16, 8), 512>>>(out);                    // launch 5
    if (out_size >= N_NODES * N_HEADS * N_HID + N_NODES * N_NODES * N_HEADS) {
        k4_transpose<<<256, 512>>>(att_out);              // launch 6
    }
}

// round 8
// speedup vs baseline: 1.3064x; 1.3064x over previous
#include <cuda_runtime.h>
#include <math.h>

#define N_NODES   512
#define IN_FEAT   512
#define N_HEADS   8
#define N_HID     64

typedef unsigned long long u64;

// Scratch (device globals: allocation-free rule)
__device__ float d_gsrc[N_HEADS * N_NODES * N_HID];   // [h][n][f]
__device__ float d_gtgt[N_HEADS * N_NODES * N_HID];   // [h][n][f]
__device__ float d_attn[N_HEADS * N_NODES * N_NODES]; // [h][i][j]
__device__ float d_u[N_HEADS * N_NODES];              // 0.6 * <w, gsrc[j]>
__device__ float d_v[N_HEADS * N_NODES];              // 0.6 * <w, gtgt[i]>
__device__ u64   d_gspk[N_HEADS * 32 * N_NODES];      // [h][fp][j] packed f-pairs

// ---- packed f32x2 helpers ----
__device__ __forceinline__ u64 pack2(float x, float y) {
    u64 r; asm("mov.b64 %0, {%1,%2};" : "=l"(r) : "f"(x), "f"(y)); return r;
}
__device__ __forceinline__ void unpack2(u64 v, float& x, float& y) {
    asm("mov.b64 {%0,%1}, %2;" : "=f"(x), "=f"(y) : "l"(v));
}
__device__ __forceinline__ u64 add2(u64 a, u64 b) {
    u64 d; asm("add.rn.f32x2 %0, %1, %2;" : "=l"(d) : "l"(a), "l"(b)); return d;
}
__device__ __forceinline__ u64 fma2(u64 a, u64 b, u64 c) {
    u64 d; asm("fma.rn.f32x2 %0, %1, %2, %3;" : "=l"(d) : "l"(a), "l"(b), "l"(c)); return d;
}

// ---------------------------------------------------------------------------
// K1 (R5 version): g = x @ W^T for both weights. 64n x 64r tile, 256 threads,
// 4x4 contiguous micro-tile, LDS.128 both operands.
// Epilogue: g rows + u/v = 0.6*<attn_w, row>.
// ---------------------------------------------------------------------------
__global__ __launch_bounds__(256) void k1_gemm(const float* __restrict__ x,
                                               const float* __restrict__ Ws,
                                               const float* __restrict__ Wt,
                                               const float* __restrict__ aw) {
    __shared__ float At[16][68];   // [d][n]
    __shared__ float Bt[16][68];   // [d][j]

    const int n0 = blockIdx.x * 64;
    const int r0 = blockIdx.y * 64;           // 0..1023
    const float* W    = (r0 < 512) ? Ws : Wt;
    float*       gout = (r0 < 512) ? d_gsrc : d_gtgt;
    float*       uv   = (r0 < 512) ? d_u : d_v;
    const int rb = r0 & 511;
    const int h  = rb >> 6;

    const int t  = threadIdx.x;
    const int tx = t & 15, ty = t >> 4;       // rows 4ty+ii, cols 4tx+q

    u64 acc[4][2] = {};

    for (int k0 = 0; k0 < IN_FEAT; k0 += 16) {
        #pragma unroll
        for (int kk = 0; kk < 4; kk++) {
            const int lin = t + kk * 256;
            const int d = lin & 15, n = lin >> 4;
            At[d][n] = x[(n0 + n) * IN_FEAT + k0 + d];
            Bt[d][n] = W[(rb + n) * IN_FEAT + k0 + d];
        }
        __syncthreads();
        #pragma unroll
        for (int d2 = 0; d2 < 16; d2++) {
            const float4 a4 = *(const float4*)&At[d2][4 * ty];
            const u64*   bp = (const u64*)&Bt[d2][4 * tx];
            const u64 b0 = bp[0], b1 = bp[1];
            const float av[4] = {a4.x, a4.y, a4.z, a4.w};
            #pragma unroll
            for (int ii = 0; ii < 4; ii++) {
                const u64 a2 = pack2(av[ii], av[ii]);
                acc[ii][0] = fma2(a2, b0, acc[ii][0]);
                acc[ii][1] = fma2(a2, b1, acc[ii][1]);
            }
        }
        __syncthreads();
    }

    const float w0 = 0.6f * aw[4 * tx],     w1 = 0.6f * aw[4 * tx + 1];
    const float w2 = 0.6f * aw[4 * tx + 2], w3 = 0.6f * aw[4 * tx + 3];

    #pragma unroll
    for (int ii = 0; ii < 4; ii++) {
        const int n = n0 + 4 * ty + ii;
        float* dst = gout + h * (N_NODES * N_HID) + n * N_HID;
        float c0, c1, c2, c3;
        unpack2(acc[ii][0], c0, c1);
        unpack2(acc[ii][1], c2, c3);
        *(float4*)&dst[4 * tx] = make_float4(c0, c1, c2, c3);
        float p = w0 * c0 + w1 * c1 + w2 * c2 + w3 * c3;
        #pragma unroll
        for (int off = 8; off; off >>= 1)
            p += __shfl_down_sync(0xffffffffu, p, off, 16);
        if (tx == 0) uv[h * N_NODES + n] = p;
    }
}

// ---------------------------------------------------------------------------
// K2pre: repack d_gsrc[h][j][f] -> d_gspk[h][fp][j] (f-pair-major u64).
// Two kernels (h-halves) so k2 lands on profiler launch slot idx5.
// ---------------------------------------------------------------------------
__global__ __launch_bounds__(256) void k2pre(int hbase) {
    const int lin = blockIdx.x * 256 + threadIdx.x;   // 0..32767
    const int h  = hbase + (lin >> 13);
    const int f4 = (lin >> 9) & 15;
    const int j  = lin & 511;
    const float4 v = *(const float4*)&d_gsrc[(h * N_NODES + j) * N_HID + 4 * f4];
    d_gspk[h * 16384 + (2 * f4)     * 512 + j] = pack2(v.x, v.y);
    d_gspk[h * 16384 + (2 * f4 + 1) * 512 + j] = pack2(v.z, v.w);
}

// ---------------------------------------------------------------------------
// K2: A[i,j] = sum_f (0.4 w_f)|gs_jf + gt_if| (f32x2 + LOP3 abs), then
// score = A + u_j + v_i, adjacency mask, softmax over j.
// Writes d_attn[h][i][j] (coalesced, for K3) AND att_out[i][j][h] directly
// (scattered stride-8 stores; L2/L1 headroom absorbs them -> no K4 kernel).
// ---------------------------------------------------------------------------
#define K2_SMEM_BYTES (32 * 512 * 8 + (32 * 66 + 64 + 512 + 32) * 4)

__global__ __launch_bounds__(512, 1) void k2_scores(const float* __restrict__ aw,
                                                    const int*   __restrict__ adj,
                                                    float*       __restrict__ att_out) {
    extern __shared__ char k2sm[];
    u64*   sgs = (u64*)k2sm;                       // [32 fp][512 j]
    float* sgt = (float*)(k2sm + 32 * 512 * 8);    // [32 i][66]
    float* sw  = sgt + 32 * 66;                    // 64 (0.4*w)
    float* su  = sw + 64;                          // 512
    float* sv  = su + 512;                         // 32

    const int h  = blockIdx.y;
    const int i0 = blockIdx.x * 32;
    const int t  = threadIdx.x;

    const float* gt_h = d_gtgt + h * (N_NODES * N_HID);

    if (t < 64) sw[t] = 0.4f * aw[t];
    su[t] = d_u[h * N_NODES + t];
    if (t < 32) sv[t] = d_v[h * N_NODES + i0 + t];

    #pragma unroll
    for (int k = 0; k < 4; k++) {
        const int lin = t + k * 512;
        const int i = lin >> 6, f = lin & 63;
        sgt[i * 66 + f] = gt_h[(i0 + i) * N_HID + f];
    }
    {
        const float4* src = (const float4*)(d_gspk + h * 16384);
        float4* dst = (float4*)sgs;
        #pragma unroll
        for (int k = 0; k < 16; k++)
            dst[t + k * 512] = src[t + k * 512];
    }
    __syncthreads();

    const int wid = t >> 5, tj = t & 31;       // warp wid owns rows 2wid, 2wid+1
    const u64 ABS2 = 0x7FFFFFFF7FFFFFFFULL;
    float vals[2][16];

    #pragma unroll
    for (int jt = 0; jt < 4; jt++) {
        u64 acc[2][4] = {};
        #pragma unroll 8
        for (int fp = 0; fp < 32; fp++) {
            const u64 w2 = *(const u64*)&sw[2 * fp];
            const u64 g0 = *(const u64*)&sgt[(2 * wid)     * 66 + 2 * fp];
            const u64 g1 = *(const u64*)&sgt[(2 * wid + 1) * 66 + 2 * fp];
            #pragma unroll
            for (int jj = 0; jj < 4; jj++) {
                const u64 s2 = sgs[fp * 512 + tj + 32 * (4 * jt + jj)];
                const u64 t0 = add2(g0, s2) & ABS2;
                const u64 t1 = add2(g1, s2) & ABS2;
                acc[0][jj] = fma2(t0, w2, acc[0][jj]);
                acc[1][jj] = fma2(t1, w2, acc[1][jj]);
            }
        }
        #pragma unroll
        for (int ii = 0; ii < 2; ii++)
            #pragma unroll
            for (int jj = 0; jj < 4; jj++) {
                float lo, hi; unpack2(acc[ii][jj], lo, hi);
                vals[ii][4 * jt + jj] = lo + hi;
            }
    }

    // Softmax per row (register-resident; lane tj holds j = tj + 32m)
    #pragma unroll
    for (int ii = 0; ii < 2; ii++) {
        const int i  = 2 * wid + ii;
        const int gi = i0 + i;
        const float svi = sv[i];
        const int* arow = adj + gi * N_NODES;

        float mx = -INFINITY;
        #pragma unroll
        for (int m = 0; m < 16; m++) {
            const int j = tj + 32 * m;
            float v = vals[ii][m] + su[j] + svi;
            v = arow[j] ? v : -INFINITY;
            vals[ii][m] = v;
            mx = fmaxf(mx, v);
        }
        #pragma unroll
        for (int o = 16; o; o >>= 1) mx = fmaxf(mx, __shfl_xor_sync(0xffffffffu, mx, o));

        float s = 0.f;
        #pragma unroll
        for (int m = 0; m < 16; m++) {
            const float e = __expf(vals[ii][m] - mx);
            vals[ii][m] = e;
            s += e;
        }
        #pragma unroll
        for (int o = 16; o; o >>= 1) s += __shfl_xor_sync(0xffffffffu, s, o);
        const float inv = 1.f / s;

        float* dst = d_attn + h * (N_NODES * N_NODES) + gi * N_NODES;
        #pragma unroll
        for (int m = 0; m < 16; m++)
            vals[ii][m] *= inv;
        #pragma unroll
        for (int m = 0; m < 16; m++)
            dst[tj + 32 * m] = vals[ii][m];
        if (att_out) {
            float* adst = att_out + gi * (N_NODES * N_HEADS) + h;
            #pragma unroll
            for (int m = 0; m < 16; m++)
                adst[(tj + 32 * m) * N_HEADS] = vals[ii][m];
        }
    }
}

// ---------------------------------------------------------------------------
// K3: out[i, h*64+f] = sum_j attn[h][i][j] * g_tgt[h][j][f]
// Row-pair f32x2 packing: attn chunk stored transposed as sa2[j][i-pair] u64
// so the A operand is one broadcast LDS.128 (4 rows) per warp per j.
// Crossbar: ~3 cyc/warp/j (was ~6).
// ---------------------------------------------------------------------------
__global__ __launch_bounds__(256) void k3_out(float* __restrict__ out) {
    __shared__ u64   sa2[32][18];   // [j][i-pair], padded (row 144 B, 16-aligned)
    __shared__ float sb[32][68];    // [j][f]

    const int i0 = blockIdx.x * 32;
    const int h  = blockIdx.y;
    const int t  = threadIdx.x;
    const int w  = t >> 5, l = t & 31;   // warp w: rows 4w..4w+3; lane l: f 2l,2l+1

    const float* attn_h = d_attn + h * (N_NODES * N_NODES);
    const float* gt_h   = d_gtgt + h * (N_NODES * N_HID);

    const int ip = t >> 4;    // 0..15 i-pair (rows 2ip, 2ip+1)
    const int j2 = t & 15;    // 0..15 j-pair group

    u64 acc[2][2] = {};       // [row-pair rp][ff]

    for (int j0 = 0; j0 < N_NODES; j0 += 32) {
        // transpose-load: sa2[j][ip] = (attn[i0+2ip][j0+j], attn[i0+2ip+1][j0+j])
        {
            const float2 r0 = *(const float2*)&attn_h[(i0 + 2 * ip)     * N_NODES + j0 + 2 * j2];
            const float2 r1 = *(const float2*)&attn_h[(i0 + 2 * ip + 1) * N_NODES + j0 + 2 * j2];
            sa2[2 * j2][ip]     = pack2(r0.x, r1.x);
            sa2[2 * j2 + 1][ip] = pack2(r0.y, r1.y);
        }
        #pragma unroll
        for (int k = 0; k < 8; k++) {
            const int lin = t + k * 256;
            const int j = lin >> 6, f = lin & 63;
            sb[j][f] = gt_h[(j0 + j) * N_HID + f];
        }
        __syncthreads();
        #pragma unroll
        for (int j = 0; j < 32; j++) {
            const u64* ap = &sa2[j][2 * w];       // LDS.128 broadcast: pairs 2w, 2w+1
            const u64 a0 = ap[0], a1 = ap[1];
            const float2 bf = *(const float2*)&sb[j][2 * l];
            const u64 b0 = pack2(bf.x, bf.x);
            const u64 b1 = pack2(bf.y, bf.y);
            acc[0][0] = fma2(a0, b0, acc[0][0]);
            acc[0][1] = fma2(a0, b1, acc[0][1]);
            acc[1][0] = fma2(a1, b0, acc[1][0]);
            acc[1][1] = fma2(a1, b1, acc[1][1]);
        }
        __syncthreads();
    }

    // acc[rp][ff]: rows (i0+4w+2rp, +1), f = 2l+ff
    #pragma unroll
    for (int rp = 0; rp < 2; rp++)
        #pragma unroll
        for (int ff = 0; ff < 2; ff++) {
            float o0, o1; unpack2(acc[rp][ff], o0, o1);
            const int i = i0 + 4 * w + 2 * rp;
            out[i       * 512 + h * N_HID + 2 * l + ff] = o0;
            out[(i + 1) * 512 + h * N_HID + 2 * l + ff] = o1;
        }
}

// ---------------------------------------------------------------------------
extern "C" void kernel_launch(void* const* d_in, const int* in_sizes, int n_in,
                              void* d_out, int out_size) {
    const float* x   = (const float*)d_in[0];  // h [1,512,512]
    const float* Ws  = (const float*)d_in[1];  // W_source [512,512]
    const float* Wt  = (const float*)d_in[2];  // W_target [512,512]
    const float* aw  = (const float*)d_in[3];  // attn_w [64]
    const int*   adj = (const int*)d_in[4];    // adjacency [512,512,1]

    float* out = (float*)d_out;
    float* att_out =
        (out_size >= N_NODES * N_HEADS * N_HID + N_NODES * N_NODES * N_HEADS)
            ? out + N_NODES * N_HEADS * N_HID : (float*)0;

    cudaFuncSetAttribute(k2_scores, cudaFuncAttributeMaxDynamicSharedMemorySize,
                         K2_SMEM_BYTES);

    k1_gemm<<<dim3(8, 16), 256>>>(x, Ws, Wt, aw);             // launch 1
    k2pre<<<128, 256>>>(0);                                    // launch 2
    k2pre<<<128, 256>>>(4);                                    // launch 3
    k2_scores<<<dim3(16, 8), 512, K2_SMEM_BYTES>>>(aw, adj, att_out); // launch 4 -> idx5
    k3_out<<<dim3(16, 8), 256>>>(out);                         // launch 5
}